// round 16
// baseline (speedup 1.0000x reference)
#include <cuda_runtime.h>
#include <cuda_bf16.h>
#include <cuda_fp16.h>

// Problem constants (fixed by the reference)
#define NSPEC      16
#define DIMRAD     16
#define DIMRADANG  8
#define NF         5          // NMAX_ANGLE + 1
#define VDIM       2
#define ROW        432        // 16 + 256 + 160
#define RAD_OFF    16
#define ANG_OFF    272
#define MAX_EDGES      1000000
#define MAX_EDGES_ANG  500000
#define MAX_ANGLES     2000000
#define MAX_ATOMS      50000
#define NB_MAX         64

#define ETA_R  10.24f                 // (16/5)^2
#define STEP_R 0.33333333333333333f   // 5/15
#define ETA2   5.2244897959183673f    // (8/3.5)^2
#define KA    (-7.5373556525f)        // -ETA2  * log2(e)
#define KR    (-14.7731972231f)       // -ETA_R * log2(e)

#define ACC_WARPS 4                   // 128-thread accum blocks

// scratch (static __device__ — zero-initialized at module load, no runtime alloc)
__device__ float4 g_eang[MAX_EDGES_ANG];     // {d, sw, v0, v1} per angular edge
__device__ int    g_cnt[2][MAX_ATOMS];       // zero at kernel_launch entry (invariant)
__device__ int    g_off[2][MAX_ATOMS + 1];
__device__ unsigned g_look[2][NB_MAX];       // lookback channels; zero at entry (invariant)
__device__ int    g_done;                    // self-resetting
__device__ int    g_rank0[MAX_ANGLES];       // per-angle rank within its central atom
__device__ int    g_rank1[MAX_EDGES];        // per-edge rank within its src atom
__device__ float4 g_arec[MAX_ANGLES];        // {d12, ca, half2(v0,v1), half2(v2,v3)}
__device__ float2 g_rrec[MAX_EDGES];         // {d, sw with species in low 4 mantissa bits}

__device__ __forceinline__ float ex2f(float x) {
    float y;
    asm("ex2.approx.ftz.f32 %0, %1;" : "=f"(y) : "f"(x));
    return y;
}

// ---------------------------------------------------------------------------
// K1: packed angular-edge table + both histograms, CACHING each element's
// rank (the atomicAdd return value) so scatter needs no atomics at all.
// ---------------------------------------------------------------------------
__global__ void prep_hist_kernel(const int* __restrict__ species,
                                 const int* __restrict__ edge_dst_ang,
                                 const float* __restrict__ vtab,
                                 const float* __restrict__ dang,
                                 const float* __restrict__ swang,
                                 const int* __restrict__ central,
                                 const int* __restrict__ esrc,
                                 int n_edges_ang, int n_angles, int n_edges) {
    int i = blockIdx.x * blockDim.x + threadIdx.x;
    if (i < n_edges_ang) {
        int s = species[edge_dst_ang[i]];
        g_eang[i] = make_float4(dang[i], swang[i],
                                vtab[s * VDIM + 0], vtab[s * VDIM + 1]);
    }
    if (i < n_angles) g_rank0[i] = atomicAdd(&g_cnt[0][central[i]], 1);
    if (i < n_edges)  g_rank1[i] = atomicAdd(&g_cnt[1][esrc[i]], 1);
}

// ---------------------------------------------------------------------------
// K2: single-pass scan (decoupled lookback), both arrays packed in u64.
// Channel word: bits[31:30] flag (0=invalid,1=aggregate,2=prefix), [29:0] value.
// All blocks (<=49) resident in one wave -> spin cannot deadlock.
// Resets g_cnt / g_look / g_done for the next call (zero invariant).
// ---------------------------------------------------------------------------
__global__ void scan_kernel(int n, int nb) {
    __shared__ unsigned long long ws[32];
    __shared__ unsigned long long s_base;
    int b = blockIdx.x, tid = threadIdx.x, lane = tid & 31, w = tid >> 5;
    int i = b * 1024 + tid;
    unsigned c0 = (i < n) ? (unsigned)g_cnt[0][i] : 0u;
    unsigned c1 = (i < n) ? (unsigned)g_cnt[1][i] : 0u;
    unsigned long long v = (unsigned long long)c0 | ((unsigned long long)c1 << 32);
    unsigned long long x = v;
    #pragma unroll
    for (int d = 1; d < 32; d <<= 1) {
        unsigned long long t = __shfl_up_sync(0xffffffffu, x, d);
        if (lane >= d) x += t;
    }
    if (lane == 31) ws[w] = x;
    __syncthreads();
    if (w == 0) {
        unsigned long long s = ws[lane];
        #pragma unroll
        for (int d = 1; d < 32; d <<= 1) {
            unsigned long long t = __shfl_up_sync(0xffffffffu, s, d);
            if (lane >= d) s += t;
        }
        ws[lane] = s;
    }
    __syncthreads();
    unsigned long long incl  = x + (w ? ws[w - 1] : 0);
    unsigned long long total = ws[31];

    if (tid == 0) {
        unsigned t0 = (unsigned)(total & 0xffffffffull);
        unsigned t1 = (unsigned)(total >> 32);
        unsigned run0 = 0, run1 = 0;
        if (b == 0) {
            ((volatile unsigned*)g_look[0])[0] = (2u << 30) | t0;
            ((volatile unsigned*)g_look[1])[0] = (2u << 30) | t1;
        } else {
            ((volatile unsigned*)g_look[0])[b] = (1u << 30) | t0;
            ((volatile unsigned*)g_look[1])[b] = (1u << 30) | t1;
            #pragma unroll 1
            for (int ch = 0; ch < 2; ch++) {
                unsigned run = 0;
                int j = b - 1;
                while (true) {
                    unsigned s = ((volatile unsigned*)g_look[ch])[j];
                    unsigned f = s >> 30;
                    if (f == 0u) continue;
                    run += s & 0x3fffffffu;
                    if (f == 2u) break;
                    j--;
                }
                if (ch == 0) run0 = run; else run1 = run;
            }
            ((volatile unsigned*)g_look[0])[b] = (2u << 30) | (run0 + t0);
            ((volatile unsigned*)g_look[1])[b] = (2u << 30) | (run1 + t1);
        }
        s_base = (unsigned long long)run0 | ((unsigned long long)run1 << 32);
    }
    __syncthreads();
    unsigned long long base = s_base;
    if (i < n) {
        int off0 = (int)((unsigned)(base & 0xffffffffull) + (unsigned)(incl & 0xffffffffull) - c0);
        int off1 = (int)((unsigned)(base >> 32) + (unsigned)(incl >> 32) - c1);
        g_off[0][i] = off0; g_cnt[0][i] = 0;
        g_off[1][i] = off1; g_cnt[1][i] = 0;
        if (i == n - 1) {
            g_off[0][n] = off0 + (int)c0;
            g_off[1][n] = off1 + (int)c1;
        }
    }
    if (tid == 0) {
        __threadfence();
        int d = atomicAdd(&g_done, 1);
        if (d == nb - 1) {               // last block: reset lookback state
            for (int j = 0; j < nb; j++) { g_look[0][j] = 0u; g_look[1][j] = 0u; }
            g_done = 0;
        }
    }
}

// ---------------------------------------------------------------------------
// K3: build records for both CSRs — NO atomics (pos = off[atom] + cached rank).
// ---------------------------------------------------------------------------
__global__ void scatter_kernel(const float* __restrict__ angles,
                               const int*  __restrict__ central,
                               const int*  __restrict__ asrc,
                               const int*  __restrict__ adst,
                               const float* __restrict__ dist,
                               const float* __restrict__ sw,
                               const int*  __restrict__ esrc,
                               const int*  __restrict__ edst,
                               const int*  __restrict__ species,
                               int n_angles, int n_edges) {
    int t = blockIdx.x * blockDim.x + threadIdx.x;
    if (t < n_angles) {
        int es = asrc[t], ed = adst[t];
        float4 ps = g_eang[es];
        float4 pd = g_eang[ed];
        float d12  = 0.5f * (ps.x + pd.x);
        float sw12 = ps.y * pd.y;
        float ca   = __cosf(angles[t]);
        float vp0 = ps.z + pd.z, vp1 = ps.w + pd.w;
        float vm0 = ps.z * pd.z, vm1 = ps.w * pd.w;
        __half2 h01 = __floats2half2_rn(sw12 * vp0 * vm0, sw12 * vp0 * vm1);
        __half2 h23 = __floats2half2_rn(sw12 * vp1 * vm0, sw12 * vp1 * vm1);
        int pos = g_off[0][central[t]] + g_rank0[t];
        float4 r;
        r.x = d12;
        r.y = ca;
        r.z = __uint_as_float(*reinterpret_cast<unsigned*>(&h01));
        r.w = __uint_as_float(*reinterpret_cast<unsigned*>(&h23));
        g_arec[pos] = r;
    }
    if (t < n_edges) {
        float d = dist[t], s = sw[t];
        int sd = species[edst[t]];
        int pos = g_off[1][esrc[t]] + g_rank1[t];
        // species in low 4 mantissa bits of sw (<=15 ulp perturbation, ~2e-6 rel)
        unsigned sb = (__float_as_uint(s) & ~15u) | (unsigned)sd;
        g_rrec[pos] = make_float2(d, __uint_as_float(sb));
    }
}

// ---------------------------------------------------------------------------
// K4: fused accumulation (frozen R11/R15 structure — 75.3us @ 32 regs).
// One warp per atom; no atomics. Scalar math, moment accumulators.
// 128-thread blocks for finer tail granularity. One-hot written here.
// ---------------------------------------------------------------------------
__global__ void accum_kernel(float* __restrict__ out,
                             const int* __restrict__ species, int n_atoms) {
    __shared__ float sacc[ACC_WARPS][2][16 * 17];
    int w    = threadIdx.x >> 5;
    int lane = threadIdx.x & 31;
    int atom = blockIdx.x * ACC_WARPS + w;
    if (atom >= n_atoms) return;

    // ---- one-hot
    if (lane < NSPEC) {
        int sp = species[atom];
        out[(long)atom * ROW + lane] = (lane == sp) ? 1.0f : 0.0f;
    }

    // ---- radial
    float* mybuf = &sacc[w][0][0];
    for (int k = lane; k < 2 * 16 * 17; k += 32) mybuf[k] = 0.f;
    __syncwarp();

    int hw = lane >> 4, lr = lane & 15;
    float ctr = STEP_R * (float)lr;
    float BR1 = -2.0f * KR * ctr;
    float BR2 = KR * ctr * ctr;
    float* hbuf = &sacc[w][hw][0] + lr * 17;
    {
        int s0 = g_off[1][atom], e0 = g_off[1][atom + 1];
        for (int i = s0 + hw; i < e0; i += 2) {
            float2 r = g_rrec[i];
            int sd = (int)(__float_as_uint(r.y) & 15u);
            float q = fmaf(KR, r.x, BR1);
            float v = r.y * ex2f(fmaf(q, r.x, BR2));
            hbuf[sd] += v;
        }
    }
    __syncwarp();
    {
        float* obase = out + (long)atom * ROW + RAD_OFF;
        #pragma unroll
        for (int k = 0; k < 8; k++) {
            int idx = k * 32 + lane;          // coalesced
            int r = idx >> 4, s = idx & 15;
            obase[idx] = sacc[w][0][r * 17 + s] + sacc[w][1][r * 17 + s];
        }
    }

    // ---- angular: lane owns (ra = lane>>2, v = lane&3); moment accumulators
    int ra = lane >> 2, v = lane & 3;
    float center = 0.5f * (float)ra;
    float B1 = -2.0f * KA * center;       // q = fma(KA, x, B1)
    float B2 = KA * center * center;      // e = fma(q, x, B2)
    bool selw = (v & 2) != 0;             // loop-invariant half selector
    int  sh   = (v & 1) << 4;             // loop-invariant shift
    float m0 = 0.f, m1 = 0.f, m2 = 0.f, m3 = 0.f, m4 = 0.f;
    int s1 = g_off[0][atom], e1 = g_off[0][atom + 1];
    const float4* __restrict__ rec = g_arec;

    int i = s1;
    for (; i + 4 <= e1; i += 4) {
        float4 p  = rec[i];
        float4 q4 = rec[i + 1];
        float4 r  = rec[i + 2];
        float4 s  = rec[i + 3];
        #pragma unroll
        for (int k = 0; k < 4; k++) {
            float4 c = (k == 0) ? p : (k == 1) ? q4 : (k == 2) ? r : s;
            unsigned u32 = selw ? __float_as_uint(c.w) : __float_as_uint(c.z);
            float val = __half2float(__ushort_as_half((unsigned short)(u32 >> sh)));
            float qq = fmaf(KA, c.x, B1);
            float tt = ex2f(fmaf(qq, c.x, B2)) * val;
            float ca = c.y;
            float ca2 = ca * ca;
            float u1  = ca * tt;
            float u2  = ca2 * tt;
            m0 += tt;
            m1 += u1;
            m2 += u2;
            m3 = fmaf(ca2, u1, m3);
            m4 = fmaf(ca2, u2, m4);
        }
    }
    for (; i < e1; i++) {
        float4 c = rec[i];
        unsigned u32 = selw ? __float_as_uint(c.w) : __float_as_uint(c.z);
        float val = __half2float(__ushort_as_half((unsigned short)(u32 >> sh)));
        float qq = fmaf(KA, c.x, B1);
        float tt = ex2f(fmaf(qq, c.x, B2)) * val;
        float ca = c.y;
        float ca2 = ca * ca;
        float u1  = ca * tt;
        float u2  = ca2 * tt;
        m0 += tt;
        m1 += u1;
        m2 += u2;
        m3 = fmaf(ca2, u1, m3);
        m4 = fmaf(ca2, u2, m4);
    }

    // cos(k*theta) recovery: a2=2m2-m0, a3=4m3-3m1, a4=8m4-8m2+m0
    float* base = out + (long)atom * ROW + ANG_OFF + ra * 20 + v;
    base[0]  = m0;
    base[4]  = m1;
    base[8]  = 2.0f * m2 - m0;
    base[12] = 4.0f * m3 - 3.0f * m1;
    base[16] = 8.0f * (m4 - m2) + m0;
}

// ---------------------------------------------------------------------------
// Launch
// ---------------------------------------------------------------------------
extern "C" void kernel_launch(void* const* d_in, const int* in_sizes, int n_in,
                              void* d_out, int out_size) {
    const int*   species      = (const int*)  d_in[0];
    const float* distances    = (const float*)d_in[1];
    const float* switch_      = (const float*)d_in[2];
    const int*   edge_src     = (const int*)  d_in[3];
    const int*   edge_dst     = (const int*)  d_in[4];
    const float* angles       = (const float*)d_in[5];
    const float* dang         = (const float*)d_in[6];
    const float* switch_ang   = (const float*)d_in[7];
    const int*   central_atom = (const int*)  d_in[8];
    const int*   angle_src    = (const int*)  d_in[9];
    const int*   angle_dst    = (const int*)  d_in[10];
    const int*   edge_dst_ang = (const int*)  d_in[11];
    const float* valence_tab  = (const float*)d_in[12];

    float* out = (float*)d_out;

    int n_atoms     = in_sizes[0];
    int n_edges     = in_sizes[1];
    int n_angles    = in_sizes[5];
    int n_edges_ang = in_sizes[6];

    // K1: edge table + histograms with rank caching
    int n1 = n_angles > n_edges ? n_angles : n_edges;
    prep_hist_kernel<<<(n1 + 255) / 256, 256>>>(species, edge_dst_ang,
                                                valence_tab, dang, switch_ang,
                                                central_atom, edge_src,
                                                n_edges_ang, n_angles, n_edges);

    // K2: single-pass decoupled-lookback scan (re-zeroes g_cnt / g_look)
    int nb = (n_atoms + 1023) / 1024;
    scan_kernel<<<nb, 1024>>>(n_atoms, nb);

    // K3: scatter records (atomic-free)
    scatter_kernel<<<(n1 + 255) / 256, 256>>>(angles, central_atom,
                                              angle_src, angle_dst,
                                              distances, switch_, edge_src,
                                              edge_dst, species,
                                              n_angles, n_edges);

    // K4: fused accumulation (one warp per atom, 128-thread blocks) + one-hot
    accum_kernel<<<(n_atoms + ACC_WARPS - 1) / ACC_WARPS, ACC_WARPS * 32>>>(
        out, species, n_atoms);
}

// round 17
// speedup vs baseline: 1.0384x; 1.0384x over previous
#include <cuda_runtime.h>
#include <cuda_bf16.h>
#include <cuda_fp16.h>

// Problem constants (fixed by the reference)
#define NSPEC      16
#define DIMRAD     16
#define DIMRADANG  8
#define NF         5          // NMAX_ANGLE + 1
#define VDIM       2
#define ROW        432        // 16 + 256 + 160
#define RAD_OFF    16
#define ANG_OFF    272
#define MAX_EDGES      1000000
#define MAX_EDGES_ANG  500000
#define MAX_ANGLES     2000000
#define MAX_ATOMS      50000
#define NB_MAX         64

#define ETA_R  10.24f                 // (16/5)^2
#define STEP_R 0.33333333333333333f   // 5/15
#define ETA2   5.2244897959183673f    // (8/3.5)^2
#define KA    (-7.5373556525f)        // -ETA2  * log2(e)
#define KR    (-14.7731972231f)       // -ETA_R * log2(e)

#define ACC_WARPS 4                   // 128-thread accum blocks

// scratch (static __device__ — zero-initialized at module load, no runtime alloc)
__device__ float4 g_eang[MAX_EDGES_ANG];     // {d, sw, v0, v1} per angular edge
__device__ int    g_cnt[2][MAX_ATOMS];       // zero at kernel_launch entry (invariant)
__device__ int    g_off[2][MAX_ATOMS + 1];
__device__ int    g_cur[2][MAX_ATOMS];
__device__ unsigned g_look[2][NB_MAX];       // lookback channels; zero at entry (invariant)
__device__ int    g_done;                    // self-resetting
__device__ float4 g_arec[MAX_ANGLES];        // {d12, ca, half2(v0,v1), half2(v2,v3)}
__device__ float2 g_rrec[MAX_EDGES];         // {d, sw with species in low 4 mantissa bits}

__device__ __forceinline__ float ex2f(float x) {
    float y;
    asm("ex2.approx.ftz.f32 %0, %1;" : "=f"(y) : "f"(x));
    return y;
}

// ---------------------------------------------------------------------------
// K1: packed angular-edge table + both histograms (one-hot lives in accum).
// ---------------------------------------------------------------------------
__global__ void prep_hist_kernel(const int* __restrict__ species,
                                 const int* __restrict__ edge_dst_ang,
                                 const float* __restrict__ vtab,
                                 const float* __restrict__ dang,
                                 const float* __restrict__ swang,
                                 const int* __restrict__ central,
                                 const int* __restrict__ esrc,
                                 int n_edges_ang, int n_angles, int n_edges) {
    int i = blockIdx.x * blockDim.x + threadIdx.x;
    if (i < n_edges_ang) {
        int s = species[edge_dst_ang[i]];
        g_eang[i] = make_float4(dang[i], swang[i],
                                vtab[s * VDIM + 0], vtab[s * VDIM + 1]);
    }
    if (i < n_angles) atomicAdd(&g_cnt[0][central[i]], 1);
    if (i < n_edges)  atomicAdd(&g_cnt[1][esrc[i]], 1);
}

// ---------------------------------------------------------------------------
// K2: single-pass scan (decoupled lookback), both arrays packed in u64.
// Channel word: bits[31:30] flag (0=invalid,1=aggregate,2=prefix), [29:0] value.
// All blocks (<=49) resident in one wave -> spin cannot deadlock.
// Resets g_cnt / g_look / g_done for the next call (zero invariant).
// ---------------------------------------------------------------------------
__global__ void scan_kernel(int n, int nb) {
    __shared__ unsigned long long ws[32];
    __shared__ unsigned long long s_base;
    int b = blockIdx.x, tid = threadIdx.x, lane = tid & 31, w = tid >> 5;
    int i = b * 1024 + tid;
    unsigned c0 = (i < n) ? (unsigned)g_cnt[0][i] : 0u;
    unsigned c1 = (i < n) ? (unsigned)g_cnt[1][i] : 0u;
    unsigned long long v = (unsigned long long)c0 | ((unsigned long long)c1 << 32);
    unsigned long long x = v;
    #pragma unroll
    for (int d = 1; d < 32; d <<= 1) {
        unsigned long long t = __shfl_up_sync(0xffffffffu, x, d);
        if (lane >= d) x += t;
    }
    if (lane == 31) ws[w] = x;
    __syncthreads();
    if (w == 0) {
        unsigned long long s = ws[lane];
        #pragma unroll
        for (int d = 1; d < 32; d <<= 1) {
            unsigned long long t = __shfl_up_sync(0xffffffffu, s, d);
            if (lane >= d) s += t;
        }
        ws[lane] = s;
    }
    __syncthreads();
    unsigned long long incl  = x + (w ? ws[w - 1] : 0);
    unsigned long long total = ws[31];

    if (tid == 0) {
        unsigned t0 = (unsigned)(total & 0xffffffffull);
        unsigned t1 = (unsigned)(total >> 32);
        unsigned run0 = 0, run1 = 0;
        if (b == 0) {
            ((volatile unsigned*)g_look[0])[0] = (2u << 30) | t0;
            ((volatile unsigned*)g_look[1])[0] = (2u << 30) | t1;
        } else {
            ((volatile unsigned*)g_look[0])[b] = (1u << 30) | t0;
            ((volatile unsigned*)g_look[1])[b] = (1u << 30) | t1;
            #pragma unroll 1
            for (int ch = 0; ch < 2; ch++) {
                unsigned run = 0;
                int j = b - 1;
                while (true) {
                    unsigned s = ((volatile unsigned*)g_look[ch])[j];
                    unsigned f = s >> 30;
                    if (f == 0u) continue;
                    run += s & 0x3fffffffu;
                    if (f == 2u) break;
                    j--;
                }
                if (ch == 0) run0 = run; else run1 = run;
            }
            ((volatile unsigned*)g_look[0])[b] = (2u << 30) | (run0 + t0);
            ((volatile unsigned*)g_look[1])[b] = (2u << 30) | (run1 + t1);
        }
        s_base = (unsigned long long)run0 | ((unsigned long long)run1 << 32);
    }
    __syncthreads();
    unsigned long long base = s_base;
    if (i < n) {
        int off0 = (int)((unsigned)(base & 0xffffffffull) + (unsigned)(incl & 0xffffffffull) - c0);
        int off1 = (int)((unsigned)(base >> 32) + (unsigned)(incl >> 32) - c1);
        g_off[0][i] = off0; g_cur[0][i] = off0; g_cnt[0][i] = 0;
        g_off[1][i] = off1; g_cur[1][i] = off1; g_cnt[1][i] = 0;
        if (i == n - 1) {
            g_off[0][n] = off0 + (int)c0;
            g_off[1][n] = off1 + (int)c1;
        }
    }
    if (tid == 0) {
        __threadfence();
        int d = atomicAdd(&g_done, 1);
        if (d == nb - 1) {               // last block: reset lookback state
            for (int j = 0; j < nb; j++) { g_look[0][j] = 0u; g_look[1][j] = 0u; }
            g_done = 0;
        }
    }
}

// ---------------------------------------------------------------------------
// K3: build records for both CSRs (atom-sorted slots). Atomics on g_cur
// (spread-address L2 atomics — measured cheaper than rank caching).
// ---------------------------------------------------------------------------
__global__ void scatter_kernel(const float* __restrict__ angles,
                               const int*  __restrict__ central,
                               const int*  __restrict__ asrc,
                               const int*  __restrict__ adst,
                               const float* __restrict__ dist,
                               const float* __restrict__ sw,
                               const int*  __restrict__ esrc,
                               const int*  __restrict__ edst,
                               const int*  __restrict__ species,
                               int n_angles, int n_edges) {
    int t = blockIdx.x * blockDim.x + threadIdx.x;
    if (t < n_angles) {
        int es = asrc[t], ed = adst[t];
        float4 ps = g_eang[es];
        float4 pd = g_eang[ed];
        float d12  = 0.5f * (ps.x + pd.x);
        float sw12 = ps.y * pd.y;
        float ca   = __cosf(angles[t]);
        float vp0 = ps.z + pd.z, vp1 = ps.w + pd.w;
        float vm0 = ps.z * pd.z, vm1 = ps.w * pd.w;
        __half2 h01 = __floats2half2_rn(sw12 * vp0 * vm0, sw12 * vp0 * vm1);
        __half2 h23 = __floats2half2_rn(sw12 * vp1 * vm0, sw12 * vp1 * vm1);
        int pos = atomicAdd(&g_cur[0][central[t]], 1);
        float4 r;
        r.x = d12;
        r.y = ca;
        r.z = __uint_as_float(*reinterpret_cast<unsigned*>(&h01));
        r.w = __uint_as_float(*reinterpret_cast<unsigned*>(&h23));
        g_arec[pos] = r;
    }
    if (t < n_edges) {
        float d = dist[t], s = sw[t];
        int sd = species[edst[t]];
        int pos = atomicAdd(&g_cur[1][esrc[t]], 1);
        // species in low 4 mantissa bits of sw (<=15 ulp perturbation, ~2e-6 rel)
        unsigned sb = (__float_as_uint(s) & ~15u) | (unsigned)sd;
        g_rrec[pos] = make_float2(d, __uint_as_float(sb));
    }
}

// ---------------------------------------------------------------------------
// K4: fused accumulation. One warp per atom; no atomics.
// Angular: half-warps process DIFFERENT records in lockstep.
//   lane = half*16 + vp*8 + ra  (ra in 0..7, vp in 0..1, half in 0..1)
//   Each lane keeps moments for its 2 v-values (10 accumulators).
//   Partials merged via shfl_xor(16) BEFORE a full-warp tail loop.
// ---------------------------------------------------------------------------
__global__ void accum_kernel(float* __restrict__ out,
                             const int* __restrict__ species, int n_atoms) {
    __shared__ float sacc[ACC_WARPS][2][16 * 17];
    int w    = threadIdx.x >> 5;
    int lane = threadIdx.x & 31;
    int atom = blockIdx.x * ACC_WARPS + w;
    if (atom >= n_atoms) return;

    // ---- one-hot
    if (lane < NSPEC) {
        int sp = species[atom];
        out[(long)atom * ROW + lane] = (lane == sp) ? 1.0f : 0.0f;
    }

    // ---- radial (unchanged R15 structure)
    float* mybuf = &sacc[w][0][0];
    for (int k = lane; k < 2 * 16 * 17; k += 32) mybuf[k] = 0.f;
    __syncwarp();

    int hwr = lane >> 4, lr = lane & 15;
    float ctr = STEP_R * (float)lr;
    float BR1 = -2.0f * KR * ctr;
    float BR2 = KR * ctr * ctr;
    float* hbuf = &sacc[w][hwr][0] + lr * 17;
    {
        int s0 = g_off[1][atom], e0 = g_off[1][atom + 1];
        for (int i = s0 + hwr; i < e0; i += 2) {
            float2 r = g_rrec[i];
            int sd = (int)(__float_as_uint(r.y) & 15u);
            float q = fmaf(KR, r.x, BR1);
            float v = r.y * ex2f(fmaf(q, r.x, BR2));
            hbuf[sd] += v;
        }
    }
    __syncwarp();
    {
        float* obase = out + (long)atom * ROW + RAD_OFF;
        #pragma unroll
        for (int k = 0; k < 8; k++) {
            int idx = k * 32 + lane;          // coalesced
            int r = idx >> 4, s = idx & 15;
            obase[idx] = sacc[w][0][r * 17 + s] + sacc[w][1][r * 17 + s];
        }
    }

    // ---- angular: lane = (half, vp, ra); halves process different records
    int ra   = lane & 7;
    int vp   = (lane >> 3) & 1;
    int half = lane >> 4;
    float center = 0.5f * (float)ra;
    float B1 = -2.0f * KA * center;       // q = fma(KA, x, B1)
    float B2 = KA * center * center;      // e = fma(q, x, B2)

    float m00 = 0.f, m01 = 0.f;           // m_k for v = 2vp (lo) and 2vp+1 (hi)
    float m10 = 0.f, m11 = 0.f;
    float m20 = 0.f, m21 = 0.f;
    float m30 = 0.f, m31 = 0.f;
    float m40 = 0.f, m41 = 0.f;

    int s1 = g_off[0][atom];
    int n  = g_off[0][atom + 1] - s1;
    const float4* __restrict__ rp = g_arec + s1;

#define ANG_PROC(c)  do {                                                    \
        unsigned u32 = vp ? __float_as_uint((c).w) : __float_as_uint((c).z); \
        __half2 hh = *reinterpret_cast<__half2*>(&u32);                      \
        float2 f = __half22float2(hh);                                       \
        float qq = fmaf(KA, (c).x, B1);                                      \
        float e  = ex2f(fmaf(qq, (c).x, B2));                                \
        float ca = (c).y;                                                    \
        float ca2 = ca * ca;                                                 \
        float t0 = e * f.x,   t1 = e * f.y;                                  \
        float u10 = ca * t0,  u11 = ca * t1;                                 \
        float u20 = ca2 * t0, u21 = ca2 * t1;                                \
        m00 += t0;  m01 += t1;                                               \
        m10 += u10; m11 += u11;                                              \
        m20 += u20; m21 += u21;                                              \
        m30 = fmaf(ca2, u10, m30); m31 = fmaf(ca2, u11, m31);                \
        m40 = fmaf(ca2, u20, m40); m41 = fmaf(ca2, u21, m41);                \
    } while (0)

    int j = 0;
    for (; j + 4 <= n; j += 4) {
        float4 cA = rp[j + half];          // half0: j,   half1: j+1
        float4 cB = rp[j + 2 + half];      // half0: j+2, half1: j+3
        ANG_PROC(cA);
        ANG_PROC(cB);
    }
    // merge cross-half partials (after this, all lanes hold full sums so far)
    m00 += __shfl_xor_sync(0xffffffffu, m00, 16);
    m01 += __shfl_xor_sync(0xffffffffu, m01, 16);
    m10 += __shfl_xor_sync(0xffffffffu, m10, 16);
    m11 += __shfl_xor_sync(0xffffffffu, m11, 16);
    m20 += __shfl_xor_sync(0xffffffffu, m20, 16);
    m21 += __shfl_xor_sync(0xffffffffu, m21, 16);
    m30 += __shfl_xor_sync(0xffffffffu, m30, 16);
    m31 += __shfl_xor_sync(0xffffffffu, m31, 16);
    m40 += __shfl_xor_sync(0xffffffffu, m40, 16);
    m41 += __shfl_xor_sync(0xffffffffu, m41, 16);
    // tail: full warp processes each remaining record once (consistent copies)
    for (; j < n; j++) {
        float4 c = rp[j];
        ANG_PROC(c);
    }
#undef ANG_PROC

    // write (half 0 only; half 1 holds identical values)
    if (half == 0) {
        float* base = out + (long)atom * ROW + ANG_OFF + ra * 20 + 2 * vp;
        base[0]  = m00;                       base[1]  = m01;
        base[4]  = m10;                       base[5]  = m11;
        base[8]  = 2.0f * m20 - m00;          base[9]  = 2.0f * m21 - m01;
        base[12] = 4.0f * m30 - 3.0f * m10;   base[13] = 4.0f * m31 - 3.0f * m11;
        base[16] = 8.0f * (m40 - m20) + m00;  base[17] = 8.0f * (m41 - m21) + m01;
    }
}

// ---------------------------------------------------------------------------
// Launch
// ---------------------------------------------------------------------------
extern "C" void kernel_launch(void* const* d_in, const int* in_sizes, int n_in,
                              void* d_out, int out_size) {
    const int*   species      = (const int*)  d_in[0];
    const float* distances    = (const float*)d_in[1];
    const float* switch_      = (const float*)d_in[2];
    const int*   edge_src     = (const int*)  d_in[3];
    const int*   edge_dst     = (const int*)  d_in[4];
    const float* angles       = (const float*)d_in[5];
    const float* dang         = (const float*)d_in[6];
    const float* switch_ang   = (const float*)d_in[7];
    const int*   central_atom = (const int*)  d_in[8];
    const int*   angle_src    = (const int*)  d_in[9];
    const int*   angle_dst    = (const int*)  d_in[10];
    const int*   edge_dst_ang = (const int*)  d_in[11];
    const float* valence_tab  = (const float*)d_in[12];

    float* out = (float*)d_out;

    int n_atoms     = in_sizes[0];
    int n_edges     = in_sizes[1];
    int n_angles    = in_sizes[5];
    int n_edges_ang = in_sizes[6];

    // K1: edge table + histograms (counters zero on entry by invariant)
    int n1 = n_angles > n_edges ? n_angles : n_edges;
    prep_hist_kernel<<<(n1 + 255) / 256, 256>>>(species, edge_dst_ang,
                                                valence_tab, dang, switch_ang,
                                                central_atom, edge_src,
                                                n_edges_ang, n_angles, n_edges);

    // K2: single-pass decoupled-lookback scan (re-zeroes g_cnt / g_look)
    int nb = (n_atoms + 1023) / 1024;
    scan_kernel<<<nb, 1024>>>(n_atoms, nb);

    // K3: scatter records
    scatter_kernel<<<(n1 + 255) / 256, 256>>>(angles, central_atom,
                                              angle_src, angle_dst,
                                              distances, switch_, edge_src,
                                              edge_dst, species,
                                              n_angles, n_edges);

    // K4: fused accumulation (one warp per atom, 128-thread blocks) + one-hot
    accum_kernel<<<(n_atoms + ACC_WARPS - 1) / ACC_WARPS, ACC_WARPS * 32>>>(
        out, species, n_atoms);
}